// round 8
// baseline (speedup 1.0000x reference)
#include <cuda_runtime.h>
#include <cuda_bf16.h>

// (B,H,N,D,K2) = (4,8,4096,64,16); FFT length 2N=8192 real -> packed 4096-pt complex FFT.
// 6 radix-4 DIF stages grouped in pairs -> 3 smem rounds fwd + 3 inv,
// mid fused at the fwd/inv boundary, pack/output fused into first/last rounds.
#define THREADS 256
// Swizzle on float4 indices; conflict-free for strides 256 (thread-consec),
// 16t within 256-blocks, and 16-blocked (stride-16 across threads).
#define SW(i) ((i) ^ (((i) >> 4) & 7))

// Packed time-domain filter a: g_pa[(h*32+dp)*4096 + tt]
__device__ float4 g_pa[256 * 4096];
// Filter spectrum, digit-reversed layout, 2 channels per float4:
// g_Af[off+p] = A[rev4(p)], g_Ag[off+p] = A[4096 - rev4(p)]
__device__ float4 g_Af[256 * 4096];
__device__ float4 g_Ag[256 * 4096];

// C16[k] = exp(-i pi k / 16)
__constant__ float2 c_C16[16] = {
    { 1.000000000000000f,  0.000000000000000f}, { 0.980785280403230f, -0.195090322016128f},
    { 0.923879532511287f, -0.382683432365090f}, { 0.831469612302545f, -0.555570233019602f},
    { 0.707106781186548f, -0.707106781186548f}, { 0.555570233019602f, -0.831469612302545f},
    { 0.382683432365090f, -0.923879532511287f}, { 0.195090322016128f, -0.980785280403230f},
    { 0.000000000000000f, -1.000000000000000f}, {-0.195090322016128f, -0.980785280403230f},
    {-0.382683432365090f, -0.923879532511287f}, {-0.555570233019602f, -0.831469612302545f},
    {-0.707106781186548f, -0.707106781186548f}, {-0.831469612302545f, -0.555570233019602f},
    {-0.923879532511287f, -0.382683432365090f}, {-0.980785280403230f, -0.195090322016128f}};

__device__ __forceinline__ float2 cmul(float2 a, float2 b) {
    return make_float2(a.x * b.x - a.y * b.y, a.x * b.y + a.y * b.x);
}
__device__ __forceinline__ float4 f4add(float4 a, float4 b) {
    return make_float4(a.x + b.x, a.y + b.y, a.z + b.z, a.w + b.w);
}
__device__ __forceinline__ float4 f4sub(float4 a, float4 b) {
    return make_float4(a.x - b.x, a.y - b.y, a.z - b.z, a.w - b.w);
}
__device__ __forceinline__ float4 f4mulni(float4 v) { return make_float4(v.y, -v.x, v.w, -v.z); }
__device__ __forceinline__ float4 f4muli(float4 v)  { return make_float4(-v.y, v.x, -v.w, v.z); }
__device__ __forceinline__ float4 f4cmul(float4 v, float2 w) {
    return make_float4(v.x * w.x - v.y * w.y, v.x * w.y + v.y * w.x,
                       v.z * w.x - v.w * w.y, v.z * w.y + v.w * w.x);
}
// reverse 6 base-4 digits of a 12-bit value
__device__ __forceinline__ int rev4_12(int v) {
    unsigned r = __brev((unsigned)v) >> 20;
    return (int)(((r & 0x555u) << 1) | ((r & 0xAAAu) >> 1));
}

// ---- radix-4 butterflies (2 packed complex channels / float4) -------------
__device__ __forceinline__ void bf4f(float4& a, float4& b, float4& c, float4& d,
                                     float2 w1, float2 w2, float2 w3) {
    float4 t0 = f4add(a, c), t1 = f4sub(a, c);
    float4 t2 = f4add(b, d), t3 = f4mulni(f4sub(b, d));
    a = f4add(t0, t2);
    b = f4cmul(f4add(t1, t3), w1);
    c = f4cmul(f4sub(t0, t2), w2);
    d = f4cmul(f4sub(t1, t3), w3);
}
__device__ __forceinline__ void bf4f0(float4& a, float4& b, float4& c, float4& d) {
    float4 t0 = f4add(a, c), t1 = f4sub(a, c);
    float4 t2 = f4add(b, d), t3 = f4mulni(f4sub(b, d));
    a = f4add(t0, t2); b = f4add(t1, t3); c = f4sub(t0, t2); d = f4sub(t1, t3);
}
__device__ __forceinline__ void bf4i(float4& a, float4& b, float4& c, float4& d,
                                     float2 w1, float2 w2, float2 w3) {
    float4 u1 = f4cmul(b, w1), u2 = f4cmul(c, w2), u3 = f4cmul(d, w3);
    float4 p = f4add(a, u2), q = f4sub(a, u2);
    float4 r = f4add(u1, u3), t = f4muli(f4sub(u1, u3));
    a = f4add(p, r); b = f4add(q, t); c = f4sub(p, r); d = f4sub(q, t);
}
__device__ __forceinline__ void bf4i0(float4& a, float4& b, float4& c, float4& d) {
    float4 p = f4add(a, c), q = f4sub(a, c);
    float4 r = f4add(b, d), t = f4muli(f4sub(b, d));
    a = f4add(p, r); b = f4add(q, t); c = f4sub(p, r); d = f4sub(q, t);
}

// ---- stage-pair rounds on 16 register-resident float4 ---------------------
// Round A fwd: stages q=1024 (t = r+4k) then q=256 (t = 4r+k); elems j0+256t.
__device__ __forceinline__ void fwd_roundA(float4* x, int j0) {
    const float2 STEP = make_float2(0.92387953251128676f, -0.38268343236508977f);
    float sn, cs;
    __sincosf(-1.5339807878856412e-3f * (float)j0, &sn, &cs);   // -2pi/4096
    float2 w = make_float2(cs, sn);
#pragma unroll
    for (int r = 0; r < 4; ++r) {
        float2 w2 = cmul(w, w), w3 = cmul(w2, w);
        bf4f(x[r], x[r + 4], x[r + 8], x[r + 12], w, w2, w3);
        w = cmul(w, STEP);
    }
    __sincosf(-6.1359231515425649e-3f * (float)j0, &sn, &cs);   // -2pi/1024
    float2 v = make_float2(cs, sn);
    float2 v2 = cmul(v, v), v3 = cmul(v2, v);
#pragma unroll
    for (int r = 0; r < 4; ++r)
        bf4f(x[4 * r], x[4 * r + 1], x[4 * r + 2], x[4 * r + 3], v, v2, v3);
}
// Round B fwd: stages q=64 (t = r+4k) then q=16 (t = 4r+k); elems 256B+j1+16t.
__device__ __forceinline__ void fwd_roundB(float4* x, int j1) {
    const float2 STEP = make_float2(0.92387953251128676f, -0.38268343236508977f);
    float sn, cs;
    __sincosf(-0.024543692606170259f * (float)j1, &sn, &cs);    // -2pi/256
    float2 w = make_float2(cs, sn);
#pragma unroll
    for (int r = 0; r < 4; ++r) {
        float2 w2 = cmul(w, w), w3 = cmul(w2, w);
        bf4f(x[r], x[r + 4], x[r + 8], x[r + 12], w, w2, w3);
        w = cmul(w, STEP);
    }
    __sincosf(-0.098174770424681035f * (float)j1, &sn, &cs);    // -2pi/64
    float2 v = make_float2(cs, sn);
    float2 v2 = cmul(v, v), v3 = cmul(v2, v);
#pragma unroll
    for (int r = 0; r < 4; ++r)
        bf4f(x[4 * r], x[4 * r + 1], x[4 * r + 2], x[4 * r + 3], v, v2, v3);
}
// Round C fwd: stages q=4 (u = j2+4k, const twiddles) then q=1; elems 16G+u.
__device__ __forceinline__ void fwd_roundC(float4* x) {
    bf4f0(x[0], x[4], x[8], x[12]);
    bf4f(x[1], x[5], x[9], x[13],
         make_float2(0.92387953f, -0.38268343f), make_float2(0.70710678f, -0.70710678f),
         make_float2(0.38268343f, -0.92387953f));
    bf4f(x[2], x[6], x[10], x[14],
         make_float2(0.70710678f, -0.70710678f), make_float2(0.f, -1.f),
         make_float2(-0.70710678f, -0.70710678f));
    bf4f(x[3], x[7], x[11], x[15],
         make_float2(0.38268343f, -0.92387953f), make_float2(-0.70710678f, -0.70710678f),
         make_float2(-0.92387953f, 0.38268343f));
#pragma unroll
    for (int r = 0; r < 4; ++r)
        bf4f0(x[4 * r], x[4 * r + 1], x[4 * r + 2], x[4 * r + 3]);
}
// Inverse mirrors (conjugate twiddles, DIT order).
__device__ __forceinline__ void inv_roundC(float4* x) {
#pragma unroll
    for (int r = 0; r < 4; ++r)
        bf4i0(x[4 * r], x[4 * r + 1], x[4 * r + 2], x[4 * r + 3]);
    bf4i0(x[0], x[4], x[8], x[12]);
    bf4i(x[1], x[5], x[9], x[13],
         make_float2(0.92387953f, 0.38268343f), make_float2(0.70710678f, 0.70710678f),
         make_float2(0.38268343f, 0.92387953f));
    bf4i(x[2], x[6], x[10], x[14],
         make_float2(0.70710678f, 0.70710678f), make_float2(0.f, 1.f),
         make_float2(-0.70710678f, 0.70710678f));
    bf4i(x[3], x[7], x[11], x[15],
         make_float2(0.38268343f, 0.92387953f), make_float2(-0.70710678f, 0.70710678f),
         make_float2(-0.92387953f, -0.38268343f));
}
__device__ __forceinline__ void inv_roundB(float4* x, int j1) {
    const float2 STEPC = make_float2(0.92387953251128676f, 0.38268343236508977f);
    float sn, cs;
    __sincosf(0.098174770424681035f * (float)j1, &sn, &cs);     // +2pi/64
    float2 v = make_float2(cs, sn);
    float2 v2 = cmul(v, v), v3 = cmul(v2, v);
#pragma unroll
    for (int r = 0; r < 4; ++r)
        bf4i(x[4 * r], x[4 * r + 1], x[4 * r + 2], x[4 * r + 3], v, v2, v3);
    __sincosf(0.024543692606170259f * (float)j1, &sn, &cs);     // +2pi/256
    float2 w = make_float2(cs, sn);
#pragma unroll
    for (int r = 0; r < 4; ++r) {
        float2 w2 = cmul(w, w), w3 = cmul(w2, w);
        bf4i(x[r], x[r + 4], x[r + 8], x[r + 12], w, w2, w3);
        w = cmul(w, STEPC);
    }
}
__device__ __forceinline__ void inv_roundA(float4* x, int j0) {
    const float2 STEPC = make_float2(0.92387953251128676f, 0.38268343236508977f);
    float sn, cs;
    __sincosf(6.1359231515425649e-3f * (float)j0, &sn, &cs);    // +2pi/1024
    float2 v = make_float2(cs, sn);
    float2 v2 = cmul(v, v), v3 = cmul(v2, v);
#pragma unroll
    for (int r = 0; r < 4; ++r)
        bf4i(x[4 * r], x[4 * r + 1], x[4 * r + 2], x[4 * r + 3], v, v2, v3);
    __sincosf(1.5339807878856412e-3f * (float)j0, &sn, &cs);    // +2pi/4096
    float2 w = make_float2(cs, sn);
#pragma unroll
    for (int r = 0; r < 4; ++r) {
        float2 w2 = cmul(w, w), w3 = cmul(w2, w);
        bf4i(x[r], x[r + 4], x[r + 8], x[r + 12], w, w2, w3);
        w = cmul(w, STEPC);
    }
}

// per-element frequency multiply: returns Z'[f] (both channels), f = rev4(p).
__device__ __forceinline__ float4 mid_zf(float4 Zf, float4 Zg, float4 Af, float4 Ag, float2 W) {
    const float s = 0.5f * (1.0f / 4096.0f);
    float4 r;
    {   // channel 0 (.xy)
        float2 E  = make_float2(0.5f * (Zf.x + Zg.x), 0.5f * (Zf.y - Zg.y));
        float2 O  = make_float2(0.5f * (Zf.y + Zg.y), -0.5f * (Zf.x - Zg.x));
        float2 WO = cmul(W, O);
        float2 Xf = make_float2(E.x + WO.x, E.y + WO.y);          // X[f]
        float2 Xg = make_float2(E.x - WO.x, -(E.y - WO.y));       // X[4096-f]
        float2 Pf = cmul(Xf, make_float2(Af.x, Af.y));
        float2 Pg = cmul(Xg, make_float2(Ag.x, Ag.y));
        float2 S  = make_float2(Pf.x + Pg.x, Pf.y - Pg.y);
        float2 D  = make_float2(Pf.x - Pg.x, Pf.y + Pg.y);
        float2 T  = cmul(make_float2(W.y, W.x), D);               // i*conj(W)*D
        r.x = s * (S.x + T.x); r.y = s * (S.y + T.y);
    }
    {   // channel 1 (.zw)
        float2 E  = make_float2(0.5f * (Zf.z + Zg.z), 0.5f * (Zf.w - Zg.w));
        float2 O  = make_float2(0.5f * (Zf.w + Zg.w), -0.5f * (Zf.z - Zg.z));
        float2 WO = cmul(W, O);
        float2 Xf = make_float2(E.x + WO.x, E.y + WO.y);
        float2 Xg = make_float2(E.x - WO.x, -(E.y - WO.y));
        float2 Pf = cmul(Xf, make_float2(Af.z, Af.w));
        float2 Pg = cmul(Xg, make_float2(Ag.z, Ag.w));
        float2 S  = make_float2(Pf.x + Pg.x, Pf.y - Pg.y);
        float2 D  = make_float2(Pf.x - Pg.x, Pf.y + Pg.y);
        float2 T  = cmul(make_float2(W.y, W.x), D);
        r.z = s * (S.x + T.x); r.w = s * (S.y + T.y);
    }
    return r;
}

// ---------------------------------------------------------------------------
// K0a: basis combine -> packed time-domain filter. grid (16, 8, 4), 512 blocks.
// ---------------------------------------------------------------------------
__global__ void __launch_bounds__(THREADS)
k_basis(const float* __restrict__ decay, const float* __restrict__ cosv,
        const float* __restrict__ coef) {
    __shared__ float scoef[16 * 64];
    int tid = threadIdx.x;
    int h = blockIdx.y;
    int tt = blockIdx.x * THREADS + tid;
    int dp0 = blockIdx.z * 8;
    for (int i = tid; i < 1024; i += THREADS) scoef[i] = coef[h * 1024 + i];
    __syncthreads();
    int t0 = 2 * tt, t1 = 2 * tt + 1;
    const float4* cos4 = (const float4*)cosv;
    float4 r0[4], r1[4];
#pragma unroll
    for (int q = 0; q < 4; ++q) { r0[q] = cos4[t0 * 4 + q]; r1[q] = cos4[t1 * 4 + q]; }
    float de0 = decay[t0], de1 = decay[t1];
#pragma unroll
    for (int dpi = 0; dpi < 8; ++dpi) {
        int dp = dp0 + dpi, d0 = dp * 2;
        float a00 = 0.f, a10 = 0.f, a01 = 0.f, a11 = 0.f;
#pragma unroll
        for (int kq = 0; kq < 4; ++kq) {
            float4 c0 = r0[kq], c1 = r1[kq];
            float w0 = scoef[(kq * 4 + 0) * 64 + d0], w1 = scoef[(kq * 4 + 1) * 64 + d0];
            float w2 = scoef[(kq * 4 + 2) * 64 + d0], w3 = scoef[(kq * 4 + 3) * 64 + d0];
            float v0 = scoef[(kq * 4 + 0) * 64 + d0 + 1], v1 = scoef[(kq * 4 + 1) * 64 + d0 + 1];
            float v2 = scoef[(kq * 4 + 2) * 64 + d0 + 1], v3 = scoef[(kq * 4 + 3) * 64 + d0 + 1];
            a00 += w0 * c0.x + w1 * c0.y + w2 * c0.z + w3 * c0.w;
            a10 += w0 * c1.x + w1 * c1.y + w2 * c1.z + w3 * c1.w;
            a01 += v0 * c0.x + v1 * c0.y + v2 * c0.z + v3 * c0.w;
            a11 += v0 * c1.x + v1 * c1.y + v2 * c1.z + v3 * c1.w;
        }
        g_pa[(size_t)(h * 32 + dp) * 4096 + tt] =
            make_float4(a00 * de0, a10 * de1, a01 * de0, a11 * de1);
    }
}

// ---------------------------------------------------------------------------
// K0b: FFT the filter; emit Af/Ag in digit-reversed layout. grid (32, 8).
// ---------------------------------------------------------------------------
__global__ void __launch_bounds__(THREADS)
k_fft_filter() {
    extern __shared__ float4 s[];
    int tid = threadIdx.x;
    int dp = blockIdx.x, h = blockIdx.y;
    size_t off = (size_t)(h * 32 + dp) * 4096;
    float4 z[16];
#pragma unroll
    for (int t = 0; t < 16; ++t) z[t] = g_pa[off + tid + 256 * t];
    fwd_roundA(z, tid);
#pragma unroll
    for (int t = 0; t < 16; ++t) s[SW(tid + 256 * t)] = z[t];
    __syncthreads();
    int j1 = tid & 15, baseB = 256 * (tid >> 4) + j1;
#pragma unroll
    for (int t = 0; t < 16; ++t) z[t] = s[SW(baseB + 16 * t)];
    fwd_roundB(z, j1);
#pragma unroll
    for (int t = 0; t < 16; ++t) s[SW(baseB + 16 * t)] = z[t];
    __syncthreads();
#pragma unroll
    for (int u = 0; u < 16; ++u) z[u] = s[SW(16 * tid + u)];
    fwd_roundC(z);
#pragma unroll
    for (int u = 0; u < 16; ++u) s[SW(16 * tid + u)] = z[u];
    __syncthreads();

    // spectrum unpack: iterate ii so that f = 16*T2 + ii (W chain in ii).
    int T2 = rev4_12(tid << 4);                     // rev4digits(tid)
    float sn, cs;
    __sincosf(-0.012271846303085130f * (float)T2, &sn, &cs);    // -pi/256
    float2 W = make_float2(cs, sn);
    const float2 SSTEP = make_float2(0.99999970586288222f, -7.6699031874270453e-4f); // exp(-i pi/4096)
#pragma unroll
    for (int ii = 0; ii < 16; ++ii) {
        int i = ((ii & 3) << 2) | (ii >> 2);        // rev2(ii)
        int p = tid + (i << 8);
        int f = (T2 << 4) | ii;
        int g = (4096 - f) & 4095;
        int pg = rev4_12(g);
        float4 Zf = s[SW(p)];
        float4 Zg = s[SW(pg)];
        float2 E0  = make_float2(0.5f * (Zf.x + Zg.x), 0.5f * (Zf.y - Zg.y));
        float2 O0  = make_float2(0.5f * (Zf.y + Zg.y), -0.5f * (Zf.x - Zg.x));
        float2 WO0 = cmul(W, O0);
        float2 E1  = make_float2(0.5f * (Zf.z + Zg.z), 0.5f * (Zf.w - Zg.w));
        float2 O1  = make_float2(0.5f * (Zf.w + Zg.w), -0.5f * (Zf.z - Zg.z));
        float2 WO1 = cmul(W, O1);
        g_Af[off + p] = make_float4(E0.x + WO0.x, E0.y + WO0.y, E1.x + WO1.x, E1.y + WO1.y);
        g_Ag[off + p] = make_float4(E0.x - WO0.x, -(E0.y - WO0.y), E1.x - WO1.x, -(E1.y - WO1.y));
        W = cmul(W, SSTEP);
    }
}

// ---------------------------------------------------------------------------
// K1: per (b,h,d-pair): x -> FFT -> multiply -> IFFT -> first N. grid (32,32).
// ---------------------------------------------------------------------------
__global__ void __launch_bounds__(THREADS)
k_conv(const float* __restrict__ x, float* __restrict__ out) {
    extern __shared__ float4 s[];
    int tid = threadIdx.x;
    int dp = blockIdx.x;
    int bh = blockIdx.y;
    int h  = bh & 7;

    // Round A fwd (fused input pack)
    const float* xb = x + (size_t)bh * 4096 * 64 + dp * 2;
    float4 z[16];
#pragma unroll
    for (int t = 0; t < 16; ++t) {
        int e = tid + 256 * t;
        if (e < 2048) {
            float2 A = *reinterpret_cast<const float2*>(xb + (size_t)(2 * e) * 64);
            float2 B = *reinterpret_cast<const float2*>(xb + (size_t)(2 * e + 1) * 64);
            z[t] = make_float4(A.x, B.x, A.y, B.y);
        } else z[t] = make_float4(0.f, 0.f, 0.f, 0.f);
    }
    fwd_roundA(z, tid);
#pragma unroll
    for (int t = 0; t < 16; ++t) s[SW(tid + 256 * t)] = z[t];
    __syncthreads();

    // Round B fwd
    int j1 = tid & 15, baseB = 256 * (tid >> 4) + j1;
#pragma unroll
    for (int t = 0; t < 16; ++t) z[t] = s[SW(baseB + 16 * t)];
    fwd_roundB(z, j1);
#pragma unroll
    for (int t = 0; t < 16; ++t) s[SW(baseB + 16 * t)] = z[t];
    __syncthreads();

    // Round C fwd (own 16-block kept in registers)
#pragma unroll
    for (int u = 0; u < 16; ++u) z[u] = s[SW(16 * tid + u)];
    fwd_roundC(z);
#pragma unroll
    for (int u = 0; u < 16; ++u) s[SW(16 * tid + u)] = z[u];
    __syncthreads();

    // Fused mid: own Zf in regs, partner Zg from smem, A from gmem.
    size_t off = (size_t)(h * 32 + dp) * 4096;
    int G2 = rev4_12(tid << 4);
    float sn, cs;
    __sincosf(-7.6699039394282061e-4f * (float)G2, &sn, &cs);   // -pi/4096
    float2 Wg = make_float2(cs, sn);
#pragma unroll
    for (int u = 0; u < 16; ++u) {
        int up = ((u & 3) << 2) | (u >> 2);
        int f = (up << 8) | G2;
        int g = (4096 - f) & 4095;
        int pq = rev4_12(g);
        float4 Zg = s[SW(pq)];
        float4 Af = g_Af[off + 16 * tid + u];
        float4 Ag = g_Ag[off + 16 * tid + u];
        float2 W = cmul(Wg, c_C16[up]);
        z[u] = mid_zf(z[u], Zg, Af, Ag, W);
    }
    __syncthreads();        // all partner reads done before overwrite

    // Round C inv (register-resident), write
    inv_roundC(z);
#pragma unroll
    for (int u = 0; u < 16; ++u) s[SW(16 * tid + u)] = z[u];
    __syncthreads();

    // Round B inv
#pragma unroll
    for (int t = 0; t < 16; ++t) z[t] = s[SW(baseB + 16 * t)];
    inv_roundB(z, j1);
#pragma unroll
    for (int t = 0; t < 16; ++t) s[SW(baseB + 16 * t)] = z[t];
    __syncthreads();

    // Round A inv (fused output store, keep first N samples: e < 2048)
#pragma unroll
    for (int t = 0; t < 16; ++t) z[t] = s[SW(tid + 256 * t)];
    inv_roundA(z, tid);
    float* ob = out + (size_t)bh * 4096 * 64 + dp * 2;
#pragma unroll
    for (int t = 0; t < 8; ++t) {
        int e = tid + 256 * t;
        *reinterpret_cast<float2*>(ob + (size_t)(2 * e) * 64)     = make_float2(z[t].x, z[t].z);
        *reinterpret_cast<float2*>(ob + (size_t)(2 * e + 1) * 64) = make_float2(z[t].y, z[t].w);
    }
}

extern "C" void kernel_launch(void* const* d_in, const int* in_sizes, int n_in,
                              void* d_out, int out_size) {
    const float* x     = (const float*)d_in[0];
    const float* decay = (const float*)d_in[1];
    const float* cosv  = (const float*)d_in[2];
    const float* coef  = (const float*)d_in[3];
    // d_in[4] = index (arange(N)) -- identity gather of first N samples.
    float* out = (float*)d_out;

    cudaFuncSetAttribute(k_fft_filter, cudaFuncAttributeMaxDynamicSharedMemorySize, 65536);
    cudaFuncSetAttribute(k_conv,       cudaFuncAttributeMaxDynamicSharedMemorySize, 65536);

    k_basis     <<<dim3(16, 8, 4), THREADS>>>(decay, cosv, coef);
    k_fft_filter<<<dim3(32, 8),    THREADS, 65536>>>();
    k_conv      <<<dim3(32, 32),   THREADS, 65536>>>(x, out);
}